// round 1
// baseline (speedup 1.0000x reference)
#include <cuda_runtime.h>

// Problem constants
#define BB 64
#define TT 8192
#define HH 8
#define HD 10
#define DD 80            // HH*HD
#define CHUNKS 16
#define ROWS_PER_CHUNK (TT / CHUNKS)   // 512

// Scratch (allocation-free rule: __device__ globals)
__device__ float g_partial[BB * CHUNKS * DD];
__device__ float g_ksum[BB * DD];

// ---------------------------------------------------------------------------
// Kernel 1: partial column sums over T. Fully coalesced: 320 threads read
// 4 consecutive rows (4*80 = 320 floats) per iteration.
// ---------------------------------------------------------------------------
__global__ void ksum_partial_kernel(const float* __restrict__ x) {
    const int blk   = blockIdx.x;
    const int b     = blk / CHUNKS;
    const int chunk = blk % CHUNKS;
    const int tid   = threadIdx.x;          // 0..319
    const int c     = tid % DD;             // column 0..79
    const int r0    = tid / DD;             // row group 0..3

    const float* p = x + ((size_t)b * TT + (size_t)chunk * ROWS_PER_CHUNK + r0) * DD + c;

    float s0 = 0.f, s1 = 0.f, s2 = 0.f, s3 = 0.f;
    // 512 rows / 4 row-groups = 128 iterations; 4-way ILP for MLP
    #pragma unroll 4
    for (int i = 0; i < ROWS_PER_CHUNK / 16; ++i) {
        s0 += p[0 * 4 * DD];
        s1 += p[1 * 4 * DD];
        s2 += p[2 * 4 * DD];
        s3 += p[3 * 4 * DD];
        p  += 16 * DD;
    }
    float s = (s0 + s1) + (s2 + s3);

    __shared__ float sh[320];
    sh[tid] = s;
    __syncthreads();
    if (tid < DD) {
        g_partial[(b * CHUNKS + chunk) * DD + tid] =
            (sh[tid] + sh[tid + DD]) + (sh[tid + 2 * DD] + sh[tid + 3 * DD]);
    }
}

// ---------------------------------------------------------------------------
// Kernel 2: fold 16 chunk partials, pre-scale by 1/sqrt(HD)
// ---------------------------------------------------------------------------
__global__ void ksum_reduce_kernel() {
    const int b = blockIdx.x;
    const int c = threadIdx.x;   // 0..79
    float s = 0.f;
    #pragma unroll
    for (int k = 0; k < CHUNKS; ++k)
        s += g_partial[(b * CHUNKS + k) * DD + c];
    g_ksum[b * DD + c] = s * 0.3162277660168379f;   // 1/sqrt(10)
}

// ---------------------------------------------------------------------------
// Kernel 3: per-(b,t) row: for each head, softmax(tanh(x*ksum_scaled)) over
// hd=10, weighted-sum with x. gate branch of the reference is identically 1
// (softmax over a size-1 axis) and is omitted.
// ---------------------------------------------------------------------------
__global__ void attn_main_kernel(const float* __restrict__ x,
                                 float* __restrict__ out) {
    const int b = blockIdx.x >> 5;                       // 32 blocks per batch
    const int t = ((blockIdx.x & 31) << 8) + threadIdx.x;

    const float2* xr = (const float2*)(x + ((size_t)b * TT + t) * DD);
    const float2* ks = (const float2*)(g_ksum + b * DD);

    #pragma unroll 1
    for (int h = 0; h < HH; ++h) {
        float xs[HD], kd[HD];
        #pragma unroll
        for (int j = 0; j < 5; ++j) {
            float2 v = __ldg(xr + h * 5 + j);
            float2 w = __ldg(ks + h * 5 + j);
            xs[2 * j]     = v.x;  xs[2 * j + 1] = v.y;
            kd[2 * j]     = w.x;  kd[2 * j + 1] = w.y;
        }

        float num = 0.f, den = 0.f;
        #pragma unroll
        for (int d = 0; d < HD; ++d) {
            float v  = xs[d] * kd[d];
            // tanh(v) = 1 - 2/(e^{2v}+1): saturates cleanly at +/-1 even when
            // e^{2v} overflows to inf or underflows to 0 (no inf/inf NaN).
            float th = 1.f - __fdividef(2.f, __expf(2.f * v) + 1.f);
            float p  = __expf(th);           // th in [-1,1] -> always safe
            den += p;
            num  = fmaf(p, xs[d], num);
        }
        out[((size_t)b * HH + h) * TT + t] = num * __fdividef(1.f, den);
    }
}

// ---------------------------------------------------------------------------
extern "C" void kernel_launch(void* const* d_in, const int* in_sizes, int n_in,
                              void* d_out, int out_size) {
    const float* x = (const float*)d_in[0];
    // d_in[1] = w_proj, d_in[2] = b_proj: mathematically dead (gate == 1)
    float* out = (float*)d_out;

    ksum_partial_kernel<<<BB * CHUNKS, 320>>>(x);
    ksum_reduce_kernel<<<BB, DD>>>();
    attn_main_kernel<<<(BB * TT) / 256, 256>>>(x, out);
}

// round 2
// speedup vs baseline: 1.1209x; 1.1209x over previous
#include <cuda_runtime.h>

// Problem constants
#define BB 64
#define TT 8192
#define HH 8
#define HD 10
#define DD 80                          // HH*HD
#define CHUNKS 16
#define ROWS_PER_CHUNK (TT / CHUNKS)   // 512
#define TILE 128                       // rows per block in main kernel
#define SROW 81                        // padded smem row stride (81*l+j mod 32 = 17l+j: conflict-free)

// Scratch (allocation-free rule: __device__ globals)
__device__ float g_partial[BB * CHUNKS * DD];

// ---------------------------------------------------------------------------
// Kernel 1: partial column sums over T. float4, fully coalesced.
// 320 threads cover 16 rows (320 float4 = 1280 floats) per slab.
// ---------------------------------------------------------------------------
__global__ void ksum_partial_kernel(const float* __restrict__ x) {
    const int blk   = blockIdx.x;
    const int b     = blk / CHUNKS;
    const int chunk = blk % CHUNKS;
    const int tid   = threadIdx.x;          // 0..319
    const int c4    = tid % 20;             // float4 column group 0..19
    const int r0    = tid / 20;             // row-in-slab 0..15

    const float4* p = (const float4*)(x + ((size_t)b * TT + (size_t)chunk * ROWS_PER_CHUNK) * DD)
                      + r0 * 20 + c4;

    float4 a0 = make_float4(0.f, 0.f, 0.f, 0.f);
    float4 a1 = make_float4(0.f, 0.f, 0.f, 0.f);
    // 512 rows / 16 rows-per-slab = 32 slabs; 2 slabs per iter for ILP
    #pragma unroll 4
    for (int i = 0; i < 16; ++i) {
        float4 v0 = p[0];
        float4 v1 = p[16 * 20];
        a0.x += v0.x; a0.y += v0.y; a0.z += v0.z; a0.w += v0.w;
        a1.x += v1.x; a1.y += v1.y; a1.z += v1.z; a1.w += v1.w;
        p += 2 * 16 * 20;
    }
    a0.x += a1.x; a0.y += a1.y; a0.z += a1.z; a0.w += a1.w;

    __shared__ float4 sh[320];
    sh[tid] = a0;
    __syncthreads();
    if (tid < 20) {
        float4 s = make_float4(0.f, 0.f, 0.f, 0.f);
        #pragma unroll
        for (int r = 0; r < 16; ++r) {
            float4 v = sh[r * 20 + tid];
            s.x += v.x; s.y += v.y; s.z += v.z; s.w += v.w;
        }
        ((float4*)&g_partial[(b * CHUNKS + chunk) * DD])[tid] = s;
    }
}

// ---------------------------------------------------------------------------
// Kernel 2 (main): per-(b,t) row, per head: softmax(tanh(x*ksum/sqrt(hd)))
// weighted-sum with x. The gate branch of the reference is softmax over a
// size-1 axis == 1.0, omitted.
// x tile staged through shared memory so global loads are fully coalesced
// (the row-per-thread direct-LDG version was L1-wavefront-bound, 16x inflation).
// ---------------------------------------------------------------------------
__global__ void attn_main_kernel(const float* __restrict__ x,
                                 float* __restrict__ out) {
    __shared__ float sx[TILE * SROW];
    __shared__ float sk[DD];

    const int tid  = threadIdx.x;              // 0..127
    const int row0 = blockIdx.x * TILE;        // global row = b*TT + t0
    const int b    = row0 / TT;                // TT % TILE == 0 -> single b per block

    // Fold the 16 chunk partials -> scaled ksum (was kernel 2; all L2 hits)
    if (tid < DD) {
        float s = 0.f;
        #pragma unroll
        for (int k = 0; k < CHUNKS; ++k)
            s += g_partial[(b * CHUNKS + k) * DD + tid];
        sk[tid] = s * 0.3162277660168379f;     // 1/sqrt(10)
    }

    // Stage 128 rows x 80 floats, coalesced float4 loads
    const float4* xs4 = (const float4*)(x + (size_t)row0 * DD);
    #pragma unroll
    for (int i = 0; i < 20; ++i) {
        int g = i * TILE + tid;                // 0..2559
        float4 v = xs4[g];
        int r = g / 20, c = g % 20;
        float* dst = &sx[r * SROW + c * 4];
        dst[0] = v.x; dst[1] = v.y; dst[2] = v.z; dst[3] = v.w;
    }
    __syncthreads();

    const float* myrow = &sx[tid * SROW];
    const int t = (row0 % TT) + tid;

    #pragma unroll 1
    for (int h = 0; h < HH; ++h) {
        float num = 0.f, den = 0.f;
        #pragma unroll
        for (int d = 0; d < HD; ++d) {
            float xv = myrow[h * HD + d];
            float v  = xv * sk[h * HD + d];
            float th;
            asm("tanh.approx.f32 %0, %1;" : "=f"(th) : "f"(v));   // 1 MUFU
            float p = __expf(th);                                 // th in [-1,1], safe
            den += p;
            num  = fmaf(p, xv, num);
        }
        out[((size_t)b * HH + h) * TT + t] = num * __fdividef(1.f, den);
    }
}

// ---------------------------------------------------------------------------
extern "C" void kernel_launch(void* const* d_in, const int* in_sizes, int n_in,
                              void* d_out, int out_size) {
    const float* x = (const float*)d_in[0];
    // d_in[1] = w_proj, d_in[2] = b_proj: mathematically dead (gate == 1)
    float* out = (float*)d_out;

    ksum_partial_kernel<<<BB * CHUNKS, 320>>>(x);
    attn_main_kernel<<<(BB * TT) / TILE, TILE>>>(x, out);
}

// round 3
// speedup vs baseline: 1.3598x; 1.2131x over previous
#include <cuda_runtime.h>

// Problem constants
#define BB 64
#define TT 8192
#define HH 8
#define HD 10
#define DD 80                          // HH*HD
#define CHUNKS 16
#define ROWS_PER_CHUNK (TT / CHUNKS)   // 512
#define TILE 128                       // rows per block in main kernel
#define SROW 81                        // padded smem row stride (81*l+j mod 32 = 17l+j: conflict-free)

// Scratch (allocation-free rule: __device__ globals)
__device__ float g_partial[BB * CHUNKS * DD];

// ---------------------------------------------------------------------------
// Kernel 1: partial column sums over T. float4, fully coalesced.
// 320 threads cover 16 rows (320 float4 = 1280 floats) per slab.
// ---------------------------------------------------------------------------
__global__ void ksum_partial_kernel(const float* __restrict__ x) {
    const int blk   = blockIdx.x;
    const int b     = blk / CHUNKS;
    const int chunk = blk % CHUNKS;
    const int tid   = threadIdx.x;          // 0..319
    const int c4    = tid % 20;             // float4 column group 0..19
    const int r0    = tid / 20;             // row-in-slab 0..15

    const float4* p = (const float4*)(x + ((size_t)b * TT + (size_t)chunk * ROWS_PER_CHUNK) * DD)
                      + r0 * 20 + c4;

    float4 a0 = make_float4(0.f, 0.f, 0.f, 0.f);
    float4 a1 = make_float4(0.f, 0.f, 0.f, 0.f);
    // 512 rows / 16 rows-per-slab = 32 slabs; 2 slabs per iter for ILP
    #pragma unroll 4
    for (int i = 0; i < 16; ++i) {
        float4 v0 = p[0];
        float4 v1 = p[16 * 20];
        a0.x += v0.x; a0.y += v0.y; a0.z += v0.z; a0.w += v0.w;
        a1.x += v1.x; a1.y += v1.y; a1.z += v1.z; a1.w += v1.w;
        p += 2 * 16 * 20;
    }
    a0.x += a1.x; a0.y += a1.y; a0.z += a1.z; a0.w += a1.w;

    __shared__ float4 sh[320];
    sh[tid] = a0;
    __syncthreads();
    if (tid < 20) {
        float4 s = make_float4(0.f, 0.f, 0.f, 0.f);
        #pragma unroll
        for (int r = 0; r < 16; ++r) {
            float4 v = sh[r * 20 + tid];
            s.x += v.x; s.y += v.y; s.z += v.z; s.w += v.w;
        }
        ((float4*)&g_partial[(b * CHUNKS + chunk) * DD])[tid] = s;
    }
}

// ---------------------------------------------------------------------------
// Kernel 2 (main): per-(b,t) row, per head: softmax(tanh(x*ksum/sqrt(hd)))
// weighted-sum with x. The gate branch of the reference is softmax over a
// size-1 axis == 1.0, omitted.
// x tile staged through shared memory so global loads are fully coalesced
// (the row-per-thread direct-LDG version was L1-wavefront-bound, 16x inflation).
// ---------------------------------------------------------------------------
__global__ void attn_main_kernel(const float* __restrict__ x,
                                 float* __restrict__ out) {
    __shared__ float sx[TILE * SROW];
    __shared__ float sk[DD];

    const int tid  = threadIdx.x;              // 0..127
    const int row0 = blockIdx.x * TILE;        // global row = b*TT + t0
    const int b    = row0 / TT;                // TT % TILE == 0 -> single b per block

    // Fold the 16 chunk partials -> scaled ksum (was kernel 2; all L2 hits)
    if (tid < DD) {
        float s = 0.f;
        #pragma unroll
        for (int k = 0; k < CHUNKS; ++k)
            s += g_partial[(b * CHUNKS + k) * DD + tid];
        sk[tid] = s * 0.3162277660168379f;     // 1/sqrt(10)
    }

    // Stage 128 rows x 80 floats, coalesced float4 loads
    const float4* xs4 = (const float4*)(x + (size_t)row0 * DD);
    #pragma unroll
    for (int i = 0; i < 20; ++i) {
        int g = i * TILE + tid;                // 0..2559
        float4 v = xs4[g];
        int r = g / 20, c = g % 20;
        float* dst = &sx[r * SROW + c * 4];
        dst[0] = v.x; dst[1] = v.y; dst[2] = v.z; dst[3] = v.w;
    }
    __syncthreads();

    const float* myrow = &sx[tid * SROW];
    const int t = (row0 % TT) + tid;

    #pragma unroll 1
    for (int h = 0; h < HH; ++h) {
        float num = 0.f, den = 0.f;
        #pragma unroll
        for (int d = 0; d < HD; ++d) {
            float xv = myrow[h * HD + d];
            float v  = xv * sk[h * HD + d];
            float th;
            asm("tanh.approx.f32 %0, %1;" : "=f"(th) : "f"(v));   // 1 MUFU
            float p = __expf(th);                                 // th in [-1,1], safe
            den += p;
            num  = fmaf(p, xv, num);
        }
        out[((size_t)b * HH + h) * TT + t] = num * __fdividef(1.f, den);
    }
}

// ---------------------------------------------------------------------------
extern "C" void kernel_launch(void* const* d_in, const int* in_sizes, int n_in,
                              void* d_out, int out_size) {
    const float* x = (const float*)d_in[0];
    // d_in[1] = w_proj, d_in[2] = b_proj: mathematically dead (gate == 1)
    float* out = (float*)d_out;

    ksum_partial_kernel<<<BB * CHUNKS, 320>>>(x);
    attn_main_kernel<<<(BB * TT) / TILE, TILE>>>(x, out);
}

// round 4
// speedup vs baseline: 1.6226x; 1.1933x over previous
#include <cuda_runtime.h>

// Problem constants
#define BB 64
#define TT 8192
#define HH 8
#define HD 10
#define DD 80                          // HH*HD
#define CHUNKS 16
#define ROWS_PER_CHUNK (TT / CHUNKS)   // 512
#define TILE 128                       // rows per block in main kernel
#define SROW 81                        // padded smem row stride (81*l mod 32 = 17l: conflict-free reads)
#define NTHR 512                       // 4 threads per row, 2 heads each

// Scratch (allocation-free rule: __device__ globals)
__device__ float g_partial[BB * CHUNKS * DD];

// ---------------------------------------------------------------------------
// Kernel 1: partial column sums over T. float4, fully coalesced.
// ---------------------------------------------------------------------------
__global__ void ksum_partial_kernel(const float* __restrict__ x) {
    const int blk   = blockIdx.x;
    const int b     = blk / CHUNKS;
    const int chunk = blk % CHUNKS;
    const int tid   = threadIdx.x;          // 0..319
    const int c4    = tid % 20;             // float4 column group 0..19
    const int r0    = tid / 20;             // row-in-slab 0..15

    const float4* p = (const float4*)(x + ((size_t)b * TT + (size_t)chunk * ROWS_PER_CHUNK) * DD)
                      + r0 * 20 + c4;

    float4 a0 = make_float4(0.f, 0.f, 0.f, 0.f);
    float4 a1 = make_float4(0.f, 0.f, 0.f, 0.f);
    #pragma unroll 4
    for (int i = 0; i < 16; ++i) {
        float4 v0 = p[0];
        float4 v1 = p[16 * 20];
        a0.x += v0.x; a0.y += v0.y; a0.z += v0.z; a0.w += v0.w;
        a1.x += v1.x; a1.y += v1.y; a1.z += v1.z; a1.w += v1.w;
        p += 2 * 16 * 20;
    }
    a0.x += a1.x; a0.y += a1.y; a0.z += a1.z; a0.w += a1.w;

    __shared__ float4 sh[320];
    sh[tid] = a0;
    __syncthreads();
    if (tid < 20) {
        float4 s = make_float4(0.f, 0.f, 0.f, 0.f);
        #pragma unroll
        for (int r = 0; r < 16; ++r) {
            float4 v = sh[r * 20 + tid];
            s.x += v.x; s.y += v.y; s.z += v.z; s.w += v.w;
        }
        ((float4*)&g_partial[(b * CHUNKS + chunk) * DD])[tid] = s;
    }
}

// ---------------------------------------------------------------------------
// Kernel 2 (main): softmax(tanh(x*ksum/sqrt(hd))) . x per (b,t,h).
// 512 threads / 128-row tile: 4 threads per row, 2 heads per thread.
// Block index remapped so earliest blocks read chunk TAILS (L2-hot from k1).
// gate branch of reference == softmax over size-1 axis == 1.0, omitted.
// ---------------------------------------------------------------------------
__global__ void attn_main_kernel(const float* __restrict__ x,
                                 float* __restrict__ out) {
    __shared__ float sx[TILE * SROW];
    __shared__ float sk[DD];

    const int tid = threadIdx.x;               // 0..511
    // Remap: sub-slab 3 of every chunk first (hottest in L2), then 2,1,0.
    const int chunk = blockIdx.x & 1023;       // (b,c) chunk id
    const int sub   = 3 - (blockIdx.x >> 10);  // slab within chunk, reversed
    const int b     = chunk >> 4;
    const int row0  = b * TT + (chunk & 15) * ROWS_PER_CHUNK + sub * TILE;

    // Fold the 16 chunk partials -> scaled ksum (all L2 hits)
    if (tid < DD) {
        float s = 0.f;
        #pragma unroll
        for (int k = 0; k < CHUNKS; ++k)
            s += g_partial[(b * CHUNKS + k) * DD + tid];
        sk[tid] = s * 0.3162277660168379f;     // 1/sqrt(10)
    }

    // Stage 128 rows x 80 floats, coalesced float4 loads
    const float4* xs4 = (const float4*)(x + (size_t)row0 * DD);
    #pragma unroll
    for (int i = 0; i < 5; ++i) {
        int g = i * NTHR + tid;                // 0..2559
        float4 v = xs4[g];
        int r = g / 20, c = g % 20;
        float* dst = &sx[r * SROW + c * 4];
        dst[0] = v.x; dst[1] = v.y; dst[2] = v.z; dst[3] = v.w;
    }
    __syncthreads();

    const int r  = tid & 127;                  // row within tile
    const int q  = tid >> 7;                   // head group 0..3
    const int h0 = q;                          // heads q and q+4
    const int h1 = q + 4;
    const float* myrow = &sx[r * SROW];
    const int t = (row0 % TT) + r;

    float num0 = 0.f, den0 = 0.f, num1 = 0.f, den1 = 0.f;
    #pragma unroll
    for (int d = 0; d < HD; ++d) {
        float xv0 = myrow[h0 * HD + d];
        float xv1 = myrow[h1 * HD + d];
        float v0  = xv0 * sk[h0 * HD + d];
        float v1  = xv1 * sk[h1 * HD + d];
        float th0, th1;
        asm("tanh.approx.f32 %0, %1;" : "=f"(th0) : "f"(v0));
        asm("tanh.approx.f32 %0, %1;" : "=f"(th1) : "f"(v1));
        float p0 = __expf(th0);                // th in [-1,1], safe
        float p1 = __expf(th1);
        den0 += p0;  num0 = fmaf(p0, xv0, num0);
        den1 += p1;  num1 = fmaf(p1, xv1, num1);
    }
    out[((size_t)b * HH + h0) * TT + t] = num0 * __fdividef(1.f, den0);
    out[((size_t)b * HH + h1) * TT + t] = num1 * __fdividef(1.f, den1);
}

// ---------------------------------------------------------------------------
extern "C" void kernel_launch(void* const* d_in, const int* in_sizes, int n_in,
                              void* d_out, int out_size) {
    const float* x = (const float*)d_in[0];
    // d_in[1] = w_proj, d_in[2] = b_proj: mathematically dead (gate == 1)
    float* out = (float*)d_out;

    ksum_partial_kernel<<<BB * CHUNKS, 320>>>(x);
    attn_main_kernel<<<(BB * TT) / TILE, NTHR>>>(x, out);
}

// round 5
// speedup vs baseline: 1.6304x; 1.0048x over previous
#include <cuda_runtime.h>

// Problem constants
#define BB 64
#define TT 8192
#define HH 8
#define HD 10
#define DD 80                          // HH*HD
#define CHUNKS 16
#define ROWS_PER_CHUNK (TT / CHUNKS)   // 512
#define TILE 128                       // rows per block in main kernel
#define SROW 81                        // padded smem row stride (81*l mod 32 = 17l: conflict-free reads)
#define NTHR 512                       // 4 threads per row, 2 heads each

// Scratch (allocation-free rule: __device__ globals)
__device__ float g_partial[BB * CHUNKS * DD];

// ---------------------------------------------------------------------------
// Kernel 1: partial column sums over T. float4, fully coalesced.
// ---------------------------------------------------------------------------
__global__ void ksum_partial_kernel(const float* __restrict__ x) {
    const int blk   = blockIdx.x;
    const int b     = blk / CHUNKS;
    const int chunk = blk % CHUNKS;
    const int tid   = threadIdx.x;          // 0..319
    const int c4    = tid % 20;             // float4 column group 0..19
    const int r0    = tid / 20;             // row-in-slab 0..15

    const float4* p = (const float4*)(x + ((size_t)b * TT + (size_t)chunk * ROWS_PER_CHUNK) * DD)
                      + r0 * 20 + c4;

    float4 a0 = make_float4(0.f, 0.f, 0.f, 0.f);
    float4 a1 = make_float4(0.f, 0.f, 0.f, 0.f);
    #pragma unroll 4
    for (int i = 0; i < 16; ++i) {
        float4 v0 = p[0];
        float4 v1 = p[16 * 20];
        a0.x += v0.x; a0.y += v0.y; a0.z += v0.z; a0.w += v0.w;
        a1.x += v1.x; a1.y += v1.y; a1.z += v1.z; a1.w += v1.w;
        p += 2 * 16 * 20;
    }
    a0.x += a1.x; a0.y += a1.y; a0.z += a1.z; a0.w += a1.w;

    __shared__ float4 sh[320];
    sh[tid] = a0;
    __syncthreads();
    if (tid < 20) {
        float4 s = make_float4(0.f, 0.f, 0.f, 0.f);
        #pragma unroll
        for (int r = 0; r < 16; ++r) {
            float4 v = sh[r * 20 + tid];
            s.x += v.x; s.y += v.y; s.z += v.z; s.w += v.w;
        }
        ((float4*)&g_partial[(b * CHUNKS + chunk) * DD])[tid] = s;
    }
}

// ---------------------------------------------------------------------------
// Kernel 2 (main): softmax(tanh(x*ksum/sqrt(hd))) . x per (b,t,h).
// 512 threads / 128-row tile: 4 threads per row, 2 heads per thread.
// Block index remapped so earliest blocks read chunk TAILS (L2-hot from k1).
// gate branch of reference == softmax over size-1 axis == 1.0, omitted.
// ---------------------------------------------------------------------------
__global__ void attn_main_kernel(const float* __restrict__ x,
                                 float* __restrict__ out) {
    __shared__ float sx[TILE * SROW];
    __shared__ float sk[DD];

    const int tid = threadIdx.x;               // 0..511
    // Remap: sub-slab 3 of every chunk first (hottest in L2), then 2,1,0.
    const int chunk = blockIdx.x & 1023;       // (b,c) chunk id
    const int sub   = 3 - (blockIdx.x >> 10);  // slab within chunk, reversed
    const int b     = chunk >> 4;
    const int row0  = b * TT + (chunk & 15) * ROWS_PER_CHUNK + sub * TILE;

    // Fold the 16 chunk partials -> scaled ksum (all L2 hits)
    if (tid < DD) {
        float s = 0.f;
        #pragma unroll
        for (int k = 0; k < CHUNKS; ++k)
            s += g_partial[(b * CHUNKS + k) * DD + tid];
        sk[tid] = s * 0.3162277660168379f;     // 1/sqrt(10)
    }

    // Stage 128 rows x 80 floats, coalesced float4 loads
    const float4* xs4 = (const float4*)(x + (size_t)row0 * DD);
    #pragma unroll
    for (int i = 0; i < 5; ++i) {
        int g = i * NTHR + tid;                // 0..2559
        float4 v = xs4[g];
        int r = g / 20, c = g % 20;
        float* dst = &sx[r * SROW + c * 4];
        dst[0] = v.x; dst[1] = v.y; dst[2] = v.z; dst[3] = v.w;
    }
    __syncthreads();

    const int r  = tid & 127;                  // row within tile
    const int q  = tid >> 7;                   // head group 0..3
    const int h0 = q;                          // heads q and q+4
    const int h1 = q + 4;
    const float* myrow = &sx[r * SROW];
    const int t = (row0 % TT) + r;

    float num0 = 0.f, den0 = 0.f, num1 = 0.f, den1 = 0.f;
    #pragma unroll
    for (int d = 0; d < HD; ++d) {
        float xv0 = myrow[h0 * HD + d];
        float xv1 = myrow[h1 * HD + d];
        float v0  = xv0 * sk[h0 * HD + d];
        float v1  = xv1 * sk[h1 * HD + d];
        float th0, th1;
        asm("tanh.approx.f32 %0, %1;" : "=f"(th0) : "f"(v0));
        asm("tanh.approx.f32 %0, %1;" : "=f"(th1) : "f"(v1));
        float p0 = __expf(th0);                // th in [-1,1], safe
        float p1 = __expf(th1);
        den0 += p0;  num0 = fmaf(p0, xv0, num0);
        den1 += p1;  num1 = fmaf(p1, xv1, num1);
    }
    out[((size_t)b * HH + h0) * TT + t] = num0 * __fdividef(1.f, den0);
    out[((size_t)b * HH + h1) * TT + t] = num1 * __fdividef(1.f, den1);
}

// ---------------------------------------------------------------------------
extern "C" void kernel_launch(void* const* d_in, const int* in_sizes, int n_in,
                              void* d_out, int out_size) {
    const float* x = (const float*)d_in[0];
    // d_in[1] = w_proj, d_in[2] = b_proj: mathematically dead (gate == 1)
    float* out = (float*)d_out;

    ksum_partial_kernel<<<BB * CHUNKS, 320>>>(x);
    attn_main_kernel<<<(BB * TT) / TILE, NTHR>>>(x, out);
}

// round 6
// speedup vs baseline: 1.6313x; 1.0005x over previous
#include <cuda_runtime.h>

// Problem constants
#define BB 64
#define TT 8192
#define HH 8
#define HD 10
#define DD 80                          // HH*HD
#define CHUNKS 16
#define ROWS_PER_CHUNK (TT / CHUNKS)   // 512
#define TILE 128                       // rows per block in main kernel
#define SROW 81                        // padded smem row stride (81*l mod 32 = 17l: conflict-free reads)
#define NTHR 512                       // 4 threads per row, 2 heads each

// Scratch (allocation-free rule: __device__ globals)
__device__ float g_partial[BB * CHUNKS * DD];

// ---------------------------------------------------------------------------
// Kernel 1: partial column sums over T. float4, fully coalesced.
// ---------------------------------------------------------------------------
__global__ void ksum_partial_kernel(const float* __restrict__ x) {
    const int blk   = blockIdx.x;
    const int b     = blk / CHUNKS;
    const int chunk = blk % CHUNKS;
    const int tid   = threadIdx.x;          // 0..319
    const int c4    = tid % 20;             // float4 column group 0..19
    const int r0    = tid / 20;             // row-in-slab 0..15

    const float4* p = (const float4*)(x + ((size_t)b * TT + (size_t)chunk * ROWS_PER_CHUNK) * DD)
                      + r0 * 20 + c4;

    float4 a0 = make_float4(0.f, 0.f, 0.f, 0.f);
    float4 a1 = make_float4(0.f, 0.f, 0.f, 0.f);
    #pragma unroll 4
    for (int i = 0; i < 16; ++i) {
        float4 v0 = p[0];
        float4 v1 = p[16 * 20];
        a0.x += v0.x; a0.y += v0.y; a0.z += v0.z; a0.w += v0.w;
        a1.x += v1.x; a1.y += v1.y; a1.z += v1.z; a1.w += v1.w;
        p += 2 * 16 * 20;
    }
    a0.x += a1.x; a0.y += a1.y; a0.z += a1.z; a0.w += a1.w;

    __shared__ float4 sh[320];
    sh[tid] = a0;
    __syncthreads();
    if (tid < 20) {
        float4 s = make_float4(0.f, 0.f, 0.f, 0.f);
        #pragma unroll
        for (int r = 0; r < 16; ++r) {
            float4 v = sh[r * 20 + tid];
            s.x += v.x; s.y += v.y; s.z += v.z; s.w += v.w;
        }
        ((float4*)&g_partial[(b * CHUNKS + chunk) * DD])[tid] = s;
    }
}

// ---------------------------------------------------------------------------
// Kernel 2 (main): softmax(tanh(x*ksum/sqrt(hd))) . x per (b,t,h).
// 512 threads / 128-row tile: 4 threads per row, 2 heads per thread.
// Block index remapped so earliest blocks read chunk TAILS (L2-hot from k1).
// gate branch of reference == softmax over size-1 axis == 1.0, omitted.
// ---------------------------------------------------------------------------
__global__ void attn_main_kernel(const float* __restrict__ x,
                                 float* __restrict__ out) {
    __shared__ float sx[TILE * SROW];
    __shared__ float sk[DD];

    const int tid = threadIdx.x;               // 0..511
    // Remap: sub-slab 3 of every chunk first (hottest in L2), then 2,1,0.
    const int chunk = blockIdx.x & 1023;       // (b,c) chunk id
    const int sub   = 3 - (blockIdx.x >> 10);  // slab within chunk, reversed
    const int b     = chunk >> 4;
    const int row0  = b * TT + (chunk & 15) * ROWS_PER_CHUNK + sub * TILE;

    // Fold the 16 chunk partials -> scaled ksum (all L2 hits)
    if (tid < DD) {
        float s = 0.f;
        #pragma unroll
        for (int k = 0; k < CHUNKS; ++k)
            s += g_partial[(b * CHUNKS + k) * DD + tid];
        sk[tid] = s * 0.3162277660168379f;     // 1/sqrt(10)
    }

    // Stage 128 rows x 80 floats, coalesced float4 loads
    const float4* xs4 = (const float4*)(x + (size_t)row0 * DD);
    #pragma unroll
    for (int i = 0; i < 5; ++i) {
        int g = i * NTHR + tid;                // 0..2559
        float4 v = xs4[g];
        int r = g / 20, c = g % 20;
        float* dst = &sx[r * SROW + c * 4];
        dst[0] = v.x; dst[1] = v.y; dst[2] = v.z; dst[3] = v.w;
    }
    __syncthreads();

    const int r  = tid & 127;                  // row within tile
    const int q  = tid >> 7;                   // head group 0..3
    const int h0 = q;                          // heads q and q+4
    const int h1 = q + 4;
    const float* myrow = &sx[r * SROW];
    const int t = (row0 % TT) + r;

    float num0 = 0.f, den0 = 0.f, num1 = 0.f, den1 = 0.f;
    #pragma unroll
    for (int d = 0; d < HD; ++d) {
        float xv0 = myrow[h0 * HD + d];
        float xv1 = myrow[h1 * HD + d];
        float v0  = xv0 * sk[h0 * HD + d];
        float v1  = xv1 * sk[h1 * HD + d];
        float th0, th1;
        asm("tanh.approx.f32 %0, %1;" : "=f"(th0) : "f"(v0));
        asm("tanh.approx.f32 %0, %1;" : "=f"(th1) : "f"(v1));
        float p0 = __expf(th0);                // th in [-1,1], safe
        float p1 = __expf(th1);
        den0 += p0;  num0 = fmaf(p0, xv0, num0);
        den1 += p1;  num1 = fmaf(p1, xv1, num1);
    }
    out[((size_t)b * HH + h0) * TT + t] = num0 * __fdividef(1.f, den0);
    out[((size_t)b * HH + h1) * TT + t] = num1 * __fdividef(1.f, den1);
}

// ---------------------------------------------------------------------------
extern "C" void kernel_launch(void* const* d_in, const int* in_sizes, int n_in,
                              void* d_out, int out_size) {
    const float* x = (const float*)d_in[0];
    // d_in[1] = w_proj, d_in[2] = b_proj: mathematically dead (gate == 1)
    float* out = (float*)d_out;

    ksum_partial_kernel<<<BB * CHUNKS, 320>>>(x);
    attn_main_kernel<<<(BB * TT) / TILE, NTHR>>>(x, out);
}

// round 7
// speedup vs baseline: 1.6340x; 1.0016x over previous
#include <cuda_runtime.h>

// Problem constants
#define BB 64
#define TT 8192
#define HH 8
#define HD 10
#define DD 80                          // HH*HD
#define CHUNKS 16
#define ROWS_PER_CHUNK (TT / CHUNKS)   // 512
#define TILE 128                       // rows per block in main kernel
#define SROW 81                        // padded smem row stride (81*l mod 32 = 17l: conflict-free reads)
#define NTHR 512                       // 4 threads per row, 2 heads each

// Scratch (allocation-free rule: __device__ globals)
__device__ float g_partial[BB * CHUNKS * DD];

// ---------------------------------------------------------------------------
// Kernel 1: partial column sums over T. float4, fully coalesced.
// ---------------------------------------------------------------------------
__global__ void ksum_partial_kernel(const float* __restrict__ x) {
    const int blk   = blockIdx.x;
    const int b     = blk / CHUNKS;
    const int chunk = blk % CHUNKS;
    const int tid   = threadIdx.x;          // 0..319
    const int c4    = tid % 20;             // float4 column group 0..19
    const int r0    = tid / 20;             // row-in-slab 0..15

    const float4* p = (const float4*)(x + ((size_t)b * TT + (size_t)chunk * ROWS_PER_CHUNK) * DD)
                      + r0 * 20 + c4;

    float4 a0 = make_float4(0.f, 0.f, 0.f, 0.f);
    float4 a1 = make_float4(0.f, 0.f, 0.f, 0.f);
    #pragma unroll 4
    for (int i = 0; i < 16; ++i) {
        float4 v0 = p[0];
        float4 v1 = p[16 * 20];
        a0.x += v0.x; a0.y += v0.y; a0.z += v0.z; a0.w += v0.w;
        a1.x += v1.x; a1.y += v1.y; a1.z += v1.z; a1.w += v1.w;
        p += 2 * 16 * 20;
    }
    a0.x += a1.x; a0.y += a1.y; a0.z += a1.z; a0.w += a1.w;

    __shared__ float4 sh[320];
    sh[tid] = a0;
    __syncthreads();
    if (tid < 20) {
        float4 s = make_float4(0.f, 0.f, 0.f, 0.f);
        #pragma unroll
        for (int r = 0; r < 16; ++r) {
            float4 v = sh[r * 20 + tid];
            s.x += v.x; s.y += v.y; s.z += v.z; s.w += v.w;
        }
        ((float4*)&g_partial[(b * CHUNKS + chunk) * DD])[tid] = s;
    }
}

// ---------------------------------------------------------------------------
// Kernel 2 (main): softmax(tanh(x*ksum/sqrt(hd))) . x per (b,t,h).
// 512 threads / 128-row tile: 4 threads per row, 2 heads per thread.
// Block index remapped so earliest blocks read chunk TAILS (L2-hot from k1).
// gate branch of reference == softmax over size-1 axis == 1.0, omitted.
// ---------------------------------------------------------------------------
__global__ void attn_main_kernel(const float* __restrict__ x,
                                 float* __restrict__ out) {
    __shared__ float sx[TILE * SROW];
    __shared__ float sk[DD];

    const int tid = threadIdx.x;               // 0..511
    // Remap: sub-slab 3 of every chunk first (hottest in L2), then 2,1,0.
    const int chunk = blockIdx.x & 1023;       // (b,c) chunk id
    const int sub   = 3 - (blockIdx.x >> 10);  // slab within chunk, reversed
    const int b     = chunk >> 4;
    const int row0  = b * TT + (chunk & 15) * ROWS_PER_CHUNK + sub * TILE;

    // Fold the 16 chunk partials -> scaled ksum (all L2 hits)
    if (tid < DD) {
        float s = 0.f;
        #pragma unroll
        for (int k = 0; k < CHUNKS; ++k)
            s += g_partial[(b * CHUNKS + k) * DD + tid];
        sk[tid] = s * 0.3162277660168379f;     // 1/sqrt(10)
    }

    // Stage 128 rows x 80 floats, coalesced float4 loads
    const float4* xs4 = (const float4*)(x + (size_t)row0 * DD);
    #pragma unroll
    for (int i = 0; i < 5; ++i) {
        int g = i * NTHR + tid;                // 0..2559
        float4 v = xs4[g];
        int r = g / 20, c = g % 20;
        float* dst = &sx[r * SROW + c * 4];
        dst[0] = v.x; dst[1] = v.y; dst[2] = v.z; dst[3] = v.w;
    }
    __syncthreads();

    const int r  = tid & 127;                  // row within tile
    const int q  = tid >> 7;                   // head group 0..3
    const int h0 = q;                          // heads q and q+4
    const int h1 = q + 4;
    const float* myrow = &sx[r * SROW];
    const int t = (row0 % TT) + r;

    float num0 = 0.f, den0 = 0.f, num1 = 0.f, den1 = 0.f;
    #pragma unroll
    for (int d = 0; d < HD; ++d) {
        float xv0 = myrow[h0 * HD + d];
        float xv1 = myrow[h1 * HD + d];
        float v0  = xv0 * sk[h0 * HD + d];
        float v1  = xv1 * sk[h1 * HD + d];
        float th0, th1;
        asm("tanh.approx.f32 %0, %1;" : "=f"(th0) : "f"(v0));
        asm("tanh.approx.f32 %0, %1;" : "=f"(th1) : "f"(v1));
        float p0 = __expf(th0);                // th in [-1,1], safe
        float p1 = __expf(th1);
        den0 += p0;  num0 = fmaf(p0, xv0, num0);
        den1 += p1;  num1 = fmaf(p1, xv1, num1);
    }
    out[((size_t)b * HH + h0) * TT + t] = num0 * __fdividef(1.f, den0);
    out[((size_t)b * HH + h1) * TT + t] = num1 * __fdividef(1.f, den1);
}

// ---------------------------------------------------------------------------
extern "C" void kernel_launch(void* const* d_in, const int* in_sizes, int n_in,
                              void* d_out, int out_size) {
    const float* x = (const float*)d_in[0];
    // d_in[1] = w_proj, d_in[2] = b_proj: mathematically dead (gate == 1)
    float* out = (float*)d_out;

    ksum_partial_kernel<<<BB * CHUNKS, 320>>>(x);
    attn_main_kernel<<<(BB * TT) / TILE, NTHR>>>(x, out);
}